// round 1
// baseline (speedup 1.0000x reference)
#include <cuda_runtime.h>
#include <math.h>
#include <stdint.h>

#define N_PTS 8192
#define D_FEAT 768

// ---------------- scratch (device globals; no allocs allowed) ----------------
__device__ int   g_fps[2][256];
__device__ float g_zstat[2][2];        // [b][0]=z mean, [b][1]=z var (ddof=1)
__device__ float g_final[2][3][256];   // per-scale scores
__device__ int   g_tok[2][40];         // selected point indices (g:0-15, c:16-31, d:32-39)

__device__ __forceinline__ float fmulr(float a, float b){ return __fmul_rn(a,b); }
__device__ __forceinline__ float faddr(float a, float b){ return __fadd_rn(a,b); }

// ---------------- FPS (one block per batch) ----------------
// Tracks min squared distance; argmax matches JAX argmax-over-sqrt exactly via
// a second pass resolving sqrt-rounding ties to the lowest index.
__global__ __launch_bounds__(1024) void fps_kernel(const float* __restrict__ coords){
    __shared__ float dist2[N_PTS];
    __shared__ float redf[32];
    __shared__ int   redi[32];
    __shared__ int   s_win;
    __shared__ float s_val;

    const int b    = blockIdx.x;
    const int tid  = threadIdx.x;
    const int lane = tid & 31;
    const int wid  = tid >> 5;
    const float* cb = coords + (size_t)b * N_PTS * 3;

    for (int j = tid; j < N_PTS; j += 1024) dist2[j] = __int_as_float(0x7f800000);

    // ---- z mean ----
    float zs = 0.f;
    for (int j = tid; j < N_PTS; j += 1024) zs += cb[j*3+2];
    for (int o = 16; o; o >>= 1) zs += __shfl_down_sync(0xffffffffu, zs, o);
    if (lane == 0) redf[wid] = zs;
    __syncthreads();
    if (wid == 0){
        float v = redf[lane];
        for (int o = 16; o; o >>= 1) v += __shfl_down_sync(0xffffffffu, v, o);
        if (lane == 0) s_val = v;
    }
    __syncthreads();
    const float zmean = s_val / (float)N_PTS;
    // ---- z var (ddof=1) ----
    float zd = 0.f;
    for (int j = tid; j < N_PTS; j += 1024){ float d = cb[j*3+2] - zmean; zd += d*d; }
    for (int o = 16; o; o >>= 1) zd += __shfl_down_sync(0xffffffffu, zd, o);
    if (lane == 0) redf[wid] = zd;
    __syncthreads();
    if (wid == 0){
        float v = redf[lane];
        for (int o = 16; o; o >>= 1) v += __shfl_down_sync(0xffffffffu, v, o);
        if (lane == 0){
            g_zstat[b][0] = zmean;
            g_zstat[b][1] = v / (float)(N_PTS - 1);
            g_fps[b][0]   = 0;
        }
    }
    __syncthreads();

    int last = 0;
    for (int s = 1; s < 256; s++){
        const float lx = cb[last*3+0], ly = cb[last*3+1], lz = cb[last*3+2];
        float bv = -1.f; int bi = N_PTS;
        for (int j = tid; j < N_PTS; j += 1024){
            float dx = cb[j*3+0] - lx;
            float dy = cb[j*3+1] - ly;
            float dz = cb[j*3+2] - lz;
            // square-then-sum, round-to-nearest, no FMA contraction (matches XLA)
            float d2 = faddr(faddr(fmulr(dx,dx), fmulr(dy,dy)), fmulr(dz,dz));
            float dm = fminf(dist2[j], d2);
            dist2[j] = dm;
            if (dm > bv){ bv = dm; bi = j; }   // ascending j -> first-index on ties
        }
        for (int o = 16; o; o >>= 1){
            float ov = __shfl_down_sync(0xffffffffu, bv, o);
            int   oi = __shfl_down_sync(0xffffffffu, bi, o);
            if (ov > bv || (ov == bv && oi < bi)){ bv = ov; bi = oi; }
        }
        if (lane == 0){ redf[wid] = bv; redi[wid] = bi; }
        __syncthreads();
        if (wid == 0){
            float v = redf[lane]; int i = redi[lane];
            for (int o = 16; o; o >>= 1){
                float ov = __shfl_down_sync(0xffffffffu, v, o);
                int   oi = __shfl_down_sync(0xffffffffu, i, o);
                if (ov > v || (ov == v && oi < i)){ v = ov; i = oi; }
            }
            if (lane == 0){ s_val = v; s_win = i; }
        }
        __syncthreads();

        // ---- pass 2: resolve sqrt-rounding ties exactly like argmax over sqrt ----
        const float m2   = s_val;
        const float sref = __fsqrt_rn(m2);
        const float thr  = m2 - m2 * 1e-6f;
        int mi = s_win;
        for (int j = tid; j < N_PTS; j += 1024){
            float v = dist2[j];
            if (v >= thr && j < mi && __fsqrt_rn(v) == sref) mi = j;
        }
        for (int o = 16; o; o >>= 1) mi = min(mi, __shfl_down_sync(0xffffffffu, mi, o));
        if (lane == 0) redi[wid] = mi;
        __syncthreads();
        if (wid == 0){
            int i = redi[lane];
            for (int o = 16; o; o >>= 1) i = min(i, __shfl_down_sync(0xffffffffu, i, o));
            if (lane == 0){ s_win = i; dist2[i] = 0.f; g_fps[b][s] = i; }
        }
        __syncthreads();
        last = s_win;
    }
}

// ---------------- scoring (8 centers per block) ----------------
__global__ __launch_bounds__(256) void score_kernel(
    const float* __restrict__ feats, const float* __restrict__ coords,
    const float* __restrict__ gW1, const float* __restrict__ gB1,
    const float* __restrict__ gW2, const float* __restrict__ gB2,
    const float* __restrict__ cW1, const float* __restrict__ cB1,
    const float* __restrict__ cW2, const float* __restrict__ cB2,
    const float* __restrict__ dW1, const float* __restrict__ dB1,
    const float* __restrict__ dW2, const float* __restrict__ dB2){

    __shared__ float feat[8][772];     // padded (772%32==4) -> conflict-free across g
    __shared__ float hid [8][260];     // padded
    __shared__ float sprob[8][16];
    __shared__ float ssaf[8];
    __shared__ int   spidx[8];
    __shared__ int   scnt[8];
    __shared__ float scc[3][8];

    const int blk = blockIdx.x;
    const int b   = blk / 56;
    const int r   = blk % 56;
    int scale, C, S, c0;
    const float *W1, *B1, *W2, *B2;
    if (r < 32){ scale=0; C=256; S=16; c0=r*8;       W1=gW1; B1=gB1; W2=gW2; B2=gB2; }
    else if (r < 48){ scale=1; C=128; S=16; c0=(r-32)*8; W1=cW1; B1=cB1; W2=cW2; B2=cB2; }
    else { scale=2; C=64; S=8; c0=(r-48)*8;          W1=dW1; B1=dB1; W2=dW2; B2=dB2; }

    const int tid = threadIdx.x;
    if (tid < 8){ spidx[tid] = g_fps[b][c0 + tid]; scnt[tid] = 0; }
    __syncthreads();

    const float* fb  = feats  + (size_t)b * N_PTS * D_FEAT;
    const float* cbp = coords + (size_t)b * N_PTS * 3;
    #pragma unroll
    for (int g = 0; g < 8; g++){
        const float* src = fb + (size_t)spidx[g] * D_FEAT;
        for (int k = tid; k < 768; k += 256) feat[g][k] = src[k];
    }
    if (tid < 8){
        int p = spidx[tid];
        scc[0][tid] = cbp[p*3+0];
        scc[1][tid] = cbp[p*3+1];
        scc[2][tid] = cbp[p*3+2];
    }
    __syncthreads();

    // hidden = relu(cfeat @ W1^T + b1), 8 centers per W1 pass
    if (tid < C){
        float acc[8];
        const float bb = B1[tid];
        #pragma unroll
        for (int g = 0; g < 8; g++) acc[g] = bb;
        const float4* w4 = reinterpret_cast<const float4*>(W1 + (size_t)tid * 768);
        for (int k4 = 0; k4 < 192; k4++){
            float4 w = __ldg(&w4[k4]);
            #pragma unroll
            for (int g = 0; g < 8; g++){
                float4 f = *reinterpret_cast<const float4*>(&feat[g][k4*4]);
                acc[g] += f.x*w.x + f.y*w.y + f.z*w.z + f.w*w.w;
            }
        }
        #pragma unroll
        for (int g = 0; g < 8; g++) hid[g][tid] = fmaxf(acc[g], 0.f);
    }
    __syncthreads();

    // logits -> sigmoid
    if (tid < 8*S){
        int g = tid / S, s = tid - g*S;
        float a = B2[s];
        const float* w2 = W2 + (size_t)s * C;
        for (int j = 0; j < C; j++) a += hid[g][j] * w2[j];
        sprob[g][s] = 1.f / (1.f + expf(-a));
    }

    // safety
    if (scale == 0){
        if (tid < 8){
            float t = (scc[2][tid] - g_zstat[b][0]) / 5.0f;
            ssaf[tid] = 1.f + (1.f / (1.f + expf(-t))) * 0.95f;
        }
    } else if (scale == 1){
        if (tid < 8) ssaf[tid] = 1.f + expf(-(g_zstat[b][1] / 0.1f)) * 0.9f;
    } else {
        int cnt[8];
        float cx[8], cy[8], cz[8], aa[8];
        #pragma unroll
        for (int g = 0; g < 8; g++){
            cnt[g] = 0;
            cx[g] = scc[0][g]; cy[g] = scc[1][g]; cz[g] = scc[2][g];
            aa[g] = faddr(faddr(fmulr(cx[g],cx[g]), fmulr(cy[g],cy[g])), fmulr(cz[g],cz[g]));
        }
        for (int j = tid; j < N_PTS; j += 256){
            float bx = cbp[j*3+0], by = cbp[j*3+1], bz = cbp[j*3+2];
            float bb = faddr(faddr(fmulr(bx,bx), fmulr(by,by)), fmulr(bz,bz));
            #pragma unroll
            for (int g = 0; g < 8; g++){
                float dt = faddr(faddr(fmulr(cx[g],bx), fmulr(cy[g],by)), fmulr(cz[g],bz));
                float d2 = faddr(faddr(aa[g], bb), -fmulr(2.0f, dt));
                if (fmaxf(d2, 0.f) < 0.25f) cnt[g]++;
            }
        }
        #pragma unroll
        for (int g = 0; g < 8; g++) atomicAdd(&scnt[g], cnt[g]);
    }
    __syncthreads();
    if (scale == 2 && tid < 8)
        ssaf[tid] = 1.f + ((float)scnt[tid] / (float)N_PTS) * 0.95f;
    __syncthreads();

    if (tid < 8){
        float m = 0.f;
        for (int s = 0; s < S; s++) m += sprob[tid][s];
        m /= (float)S;
        g_final[b][scale][c0 + tid] = m * ssaf[tid];
    }
}

// ---------------- stable top-k (matches lax.top_k tie semantics) ----------------
__global__ __launch_bounds__(32) void topk_kernel(){
    const int blk = blockIdx.x;
    const int b = blk / 3, sc = blk % 3;
    const int C   = (sc == 0) ? 256 : (sc == 1 ? 128 : 64);
    const int S   = (sc == 2) ? 8 : 16;
    const int off = (sc == 0) ? 0 : (sc == 1 ? 16 : 32);
    const int lane = threadIdx.x;

    __shared__ float fv[256];
    __shared__ int   taken[256];
    for (int j = lane; j < C; j += 32){ fv[j] = g_final[b][sc][j]; taken[j] = 0; }
    __syncwarp();

    for (int t = 0; t < S; t++){
        float bv = -1e30f; int bi = C;
        for (int j = lane; j < C; j += 32){
            if (!taken[j]){
                float v = fv[j];
                if (v > bv || (v == bv && j < bi)){ bv = v; bi = j; }
            }
        }
        for (int o = 16; o; o >>= 1){
            float ov = __shfl_down_sync(0xffffffffu, bv, o);
            int   oi = __shfl_down_sync(0xffffffffu, bi, o);
            if (ov > bv || (ov == bv && oi < bi)){ bv = ov; bi = oi; }
        }
        bi = __shfl_sync(0xffffffffu, bi, 0);
        if (lane == 0){ taken[bi] = 1; g_tok[b][off + t] = g_fps[b][bi]; }
        __syncwarp();
    }
}

// ---------------- token MLP + LayerNorm (one block per token) ----------------
__global__ __launch_bounds__(384) void mlp_kernel(const float* __restrict__ feats,
    const float* __restrict__ pW1, const float* __restrict__ pb1,
    const float* __restrict__ pW2, const float* __restrict__ pb2,
    const float* __restrict__ lng, const float* __restrict__ lnb,
    float* __restrict__ out){

    __shared__ float feat[768];
    __shared__ float hid[384];
    __shared__ float ov[768];
    __shared__ float red[32];

    const int blk = blockIdx.x;
    const int b = blk / 40, t = blk % 40;
    const int tid = threadIdx.x, lane = tid & 31, wid = tid >> 5;

    const int src = g_tok[b][t];
    const float* fs = feats + ((size_t)b * N_PTS + src) * D_FEAT;
    for (int k = tid; k < 768; k += 384) feat[k] = fs[k];
    __syncthreads();

    {   // hid = relu(tok @ pW1^T + pb1)
        float a = pb1[tid];
        const float4* w4 = reinterpret_cast<const float4*>(pW1 + (size_t)tid * 768);
        for (int k = 0; k < 192; k++){
            float4 w = __ldg(&w4[k]);
            float4 f = *reinterpret_cast<const float4*>(&feat[k*4]);
            a += f.x*w.x + f.y*w.y + f.z*w.z + f.w*w.w;
        }
        hid[tid] = fmaxf(a, 0.f);
    }
    __syncthreads();

    #pragma unroll
    for (int h = 0; h < 2; h++){
        int o = tid + h * 384;
        float a = pb2[o];
        const float4* w4 = reinterpret_cast<const float4*>(pW2 + (size_t)o * 384);
        for (int k = 0; k < 96; k++){
            float4 w = __ldg(&w4[k]);
            float4 f = *reinterpret_cast<const float4*>(&hid[k*4]);
            a += f.x*w.x + f.y*w.y + f.z*w.z + f.w*w.w;
        }
        ov[o] = a;
    }
    __syncthreads();

    // LayerNorm over 768
    float s = ov[tid] + ov[tid + 384];
    for (int o = 16; o; o >>= 1) s += __shfl_down_sync(0xffffffffu, s, o);
    if (lane == 0) red[wid] = s;
    __syncthreads();
    if (tid < 32){
        float v = (tid < 12) ? red[tid] : 0.f;
        for (int o = 16; o; o >>= 1) v += __shfl_down_sync(0xffffffffu, v, o);
        if (tid == 0) red[0] = v;
    }
    __syncthreads();
    const float mu = red[0] * (1.f / 768.f);
    __syncthreads();

    const float d0 = ov[tid] - mu, d1 = ov[tid + 384] - mu;
    float s2 = d0*d0 + d1*d1;
    for (int o = 16; o; o >>= 1) s2 += __shfl_down_sync(0xffffffffu, s2, o);
    if (lane == 0) red[wid] = s2;
    __syncthreads();
    if (tid < 32){
        float v = (tid < 12) ? red[tid] : 0.f;
        for (int o = 16; o; o >>= 1) v += __shfl_down_sync(0xffffffffu, v, o);
        if (tid == 0) red[0] = v;
    }
    __syncthreads();
    const float var = red[0] * (1.f / 768.f);
    const float rs  = rsqrtf(var + 1e-5f);

    float* op = out + ((size_t)(b * 40 + t)) * 768;
    op[tid]       = d0 * rs * lng[tid]       + lnb[tid];
    op[tid + 384] = d1 * rs * lng[tid + 384] + lnb[tid + 384];
}

// ---------------- launch ----------------
extern "C" void kernel_launch(void* const* d_in, const int* in_sizes, int n_in,
                              void* d_out, int out_size){
    const float* feats  = (const float*)d_in[0];
    const float* coords = (const float*)d_in[1];
    const float* gW1 = (const float*)d_in[2];
    const float* gB1 = (const float*)d_in[3];
    const float* gW2 = (const float*)d_in[4];
    const float* gB2 = (const float*)d_in[5];
    const float* cW1 = (const float*)d_in[6];
    const float* cB1 = (const float*)d_in[7];
    const float* cW2 = (const float*)d_in[8];
    const float* cB2 = (const float*)d_in[9];
    const float* dW1 = (const float*)d_in[10];
    const float* dB1 = (const float*)d_in[11];
    const float* dW2 = (const float*)d_in[12];
    const float* dB2 = (const float*)d_in[13];
    const float* pW1 = (const float*)d_in[14];
    const float* pb1 = (const float*)d_in[15];
    const float* pW2 = (const float*)d_in[16];
    const float* pb2 = (const float*)d_in[17];
    const float* lng = (const float*)d_in[18];
    const float* lnb = (const float*)d_in[19];
    float* out = (float*)d_out;

    fps_kernel<<<2, 1024>>>(coords);
    score_kernel<<<112, 256>>>(feats, coords,
                               gW1, gB1, gW2, gB2,
                               cW1, cB1, cW2, cB2,
                               dW1, dB1, dW2, dB2);
    topk_kernel<<<6, 32>>>();
    mlp_kernel<<<80, 384>>>(feats, pW1, pb1, pW2, pb2, lng, lnb, out);
}

// round 2
// speedup vs baseline: 1.0218x; 1.0218x over previous
#include <cuda_runtime.h>
#include <math.h>
#include <stdint.h>

#define N_PTS 8192
#define D_FEAT 768

// ---------------- scratch (device globals; no allocs allowed) ----------------
__device__ int   g_fps[2][256];
__device__ float g_zstat[2][2];        // [b][0]=z mean, [b][1]=z var (ddof=1)
__device__ float g_final[2][3][256];   // per-scale scores
__device__ int   g_tok[2][40];         // selected point indices (g:0-15, c:16-31, d:32-39)

__device__ __forceinline__ float fmulr(float a, float b){ return __fmul_rn(a,b); }
__device__ __forceinline__ float faddr(float a, float b){ return __fadd_rn(a,b); }

// ---- packed f32x2 helpers (Blackwell sm_103a) — per-lane IEEE RN, bit-identical
// to scalar __fadd_rn/__fmul_rn, so FPS selection stays exact.
__device__ __forceinline__ unsigned long long pk2(float lo, float hi){
    unsigned long long r;
    asm("mov.b64 %0, {%1, %2};" : "=l"(r) : "f"(lo), "f"(hi));
    return r;
}
__device__ __forceinline__ void upk2(unsigned long long v, float& lo, float& hi){
    asm("mov.b64 {%0, %1}, %2;" : "=f"(lo), "=f"(hi) : "l"(v));
}
__device__ __forceinline__ unsigned long long add2(unsigned long long a, unsigned long long b){
    unsigned long long r;
    asm("add.rn.f32x2 %0, %1, %2;" : "=l"(r) : "l"(a), "l"(b));
    return r;
}
__device__ __forceinline__ unsigned long long mul2(unsigned long long a, unsigned long long b){
    unsigned long long r;
    asm("mul.rn.f32x2 %0, %1, %2;" : "=l"(r) : "l"(a), "l"(b));
    return r;
}

// ---------------- FPS (one block per batch, register-resident) ----------------
// Tracks min squared distance per point in registers; argmax matches JAX
// argmax-over-sqrt exactly via a cheap tie-resolution pass (sqrt rounding ties
// resolved to the lowest index with atomicMin).
__global__ __launch_bounds__(1024) void fps_kernel(const float* __restrict__ coords){
    __shared__ float redf[32];
    __shared__ int   redi[32];
    __shared__ float s_last[3];
    __shared__ float s_val;
    __shared__ int   s_win;

    const int b    = blockIdx.x;
    const int tid  = threadIdx.x;
    const int lane = tid & 31;
    const int wid  = tid >> 5;
    const float* cb = coords + (size_t)b * N_PTS * 3;

    // Each thread owns points j = tid + k*1024, k=0..7 (coords + d2 in regs).
    float px[8], py[8], pz[8], d2[8];
    float zs = 0.f;
    #pragma unroll
    for (int k = 0; k < 8; k++){
        const int j = tid + (k << 10);
        px[k] = cb[j*3+0];
        py[k] = cb[j*3+1];
        pz[k] = cb[j*3+2];
        d2[k] = __int_as_float(0x7f800000);
        zs += pz[k];
    }
    unsigned long long px2[4], py2[4], pz2[4];
    #pragma unroll
    for (int k = 0; k < 4; k++){
        px2[k] = pk2(px[2*k], px[2*k+1]);
        py2[k] = pk2(py[2*k], py[2*k+1]);
        pz2[k] = pk2(pz[2*k], pz[2*k+1]);
    }

    // ---- z mean ----
    for (int o = 16; o; o >>= 1) zs += __shfl_down_sync(0xffffffffu, zs, o);
    if (lane == 0) redf[wid] = zs;
    __syncthreads();
    if (wid == 0){
        float v = redf[lane];
        for (int o = 16; o; o >>= 1) v += __shfl_down_sync(0xffffffffu, v, o);
        if (lane == 0) s_val = v;
    }
    __syncthreads();
    const float zmean = s_val / (float)N_PTS;
    // ---- z var (ddof=1) ----
    float zd = 0.f;
    #pragma unroll
    for (int k = 0; k < 8; k++){ float d = pz[k] - zmean; zd += d*d; }
    for (int o = 16; o; o >>= 1) zd += __shfl_down_sync(0xffffffffu, zd, o);
    if (lane == 0) redf[wid] = zd;
    __syncthreads();
    if (wid == 0){
        float v = redf[lane];
        for (int o = 16; o; o >>= 1) v += __shfl_down_sync(0xffffffffu, v, o);
        if (lane == 0){
            g_zstat[b][0] = zmean;
            g_zstat[b][1] = v / (float)(N_PTS - 1);
            g_fps[b][0]   = 0;
        }
    }
    if (tid == 0){ s_last[0] = cb[0]; s_last[1] = cb[1]; s_last[2] = cb[2]; }
    __syncthreads();

    for (int s = 1; s < 256; s++){
        const float lx = s_last[0], ly = s_last[1], lz = s_last[2];
        const unsigned long long nlx2 = pk2(-lx, -lx);
        const unsigned long long nly2 = pk2(-ly, -ly);
        const unsigned long long nlz2 = pk2(-lz, -lz);

        float bv = -1.f; int bi = N_PTS;
        #pragma unroll
        for (int k = 0; k < 4; k++){
            // (p - L) via p + (-L): exact sub; square-then-sum, (x2+y2)+z2 order
            unsigned long long dx = add2(px2[k], nlx2);
            unsigned long long dy = add2(py2[k], nly2);
            unsigned long long dz = add2(pz2[k], nlz2);
            unsigned long long sm = add2(add2(mul2(dx,dx), mul2(dy,dy)), mul2(dz,dz));
            float lo, hi; upk2(sm, lo, hi);
            float dm0 = fminf(d2[2*k],   lo);
            float dm1 = fminf(d2[2*k+1], hi);
            d2[2*k]   = dm0;
            d2[2*k+1] = dm1;
            if (dm0 > bv){ bv = dm0; bi = tid + ((2*k)   << 10); }
            if (dm1 > bv){ bv = dm1; bi = tid + ((2*k+1) << 10); }
        }
        // warp reduce (max value, min index on ties)
        for (int o = 16; o; o >>= 1){
            float ov = __shfl_down_sync(0xffffffffu, bv, o);
            int   oi = __shfl_down_sync(0xffffffffu, bi, o);
            if (ov > bv || (ov == bv && oi < bi)){ bv = ov; bi = oi; }
        }
        if (lane == 0){ redf[wid] = bv; redi[wid] = bi; }
        __syncthreads();
        if (wid == 0){
            float v = redf[lane]; int i = redi[lane];
            for (int o = 16; o; o >>= 1){
                float ov = __shfl_down_sync(0xffffffffu, v, o);
                int   oi = __shfl_down_sync(0xffffffffu, i, o);
                if (ov > v || (ov == v && oi < i)){ v = ov; i = oi; }
            }
            if (lane == 0){ s_val = v; s_win = i; }
        }
        __syncthreads();

        // ---- tie resolution: first index whose sqrt rounds to sqrt(max) ----
        const float m2   = s_val;
        const float thr  = m2 - m2 * 1e-6f;
        const float sref = __fsqrt_rn(m2);
        const int swin = s_win;
        #pragma unroll
        for (int k = 0; k < 8; k++){
            const int j = tid + (k << 10);
            if (d2[k] >= thr && j < swin){
                if (__fsqrt_rn(d2[k]) == sref) atomicMin(&s_win, j);
            }
        }
        __syncthreads();
        const int w = s_win;
        if ((w & 1023) == tid){
            const int k = w >> 10;
            d2[k] = 0.f;
            s_last[0] = px[k]; s_last[1] = py[k]; s_last[2] = pz[k];
            g_fps[b][s] = w;
        }
        __syncthreads();
    }
}

// ---------------- scoring (8 centers per block) ----------------
__global__ __launch_bounds__(256) void score_kernel(
    const float* __restrict__ feats, const float* __restrict__ coords,
    const float* __restrict__ gW1, const float* __restrict__ gB1,
    const float* __restrict__ gW2, const float* __restrict__ gB2,
    const float* __restrict__ cW1, const float* __restrict__ cB1,
    const float* __restrict__ cW2, const float* __restrict__ cB2,
    const float* __restrict__ dW1, const float* __restrict__ dB1,
    const float* __restrict__ dW2, const float* __restrict__ dB2){

    __shared__ float feat[8][772];
    __shared__ float hid [8][260];
    __shared__ float sprob[8][16];
    __shared__ float ssaf[8];
    __shared__ int   spidx[8];
    __shared__ int   scnt[8];
    __shared__ float scc[3][8];

    const int blk = blockIdx.x;
    const int b   = blk / 56;
    const int r   = blk % 56;
    int scale, C, S, c0;
    const float *W1, *B1, *W2, *B2;
    if (r < 32){ scale=0; C=256; S=16; c0=r*8;       W1=gW1; B1=gB1; W2=gW2; B2=gB2; }
    else if (r < 48){ scale=1; C=128; S=16; c0=(r-32)*8; W1=cW1; B1=cB1; W2=cW2; B2=cB2; }
    else { scale=2; C=64; S=8; c0=(r-48)*8;          W1=dW1; B1=dB1; W2=dW2; B2=dB2; }

    const int tid = threadIdx.x;
    if (tid < 8){ spidx[tid] = g_fps[b][c0 + tid]; scnt[tid] = 0; }
    __syncthreads();

    const float* fb  = feats  + (size_t)b * N_PTS * D_FEAT;
    const float* cbp = coords + (size_t)b * N_PTS * 3;
    #pragma unroll
    for (int g = 0; g < 8; g++){
        const float* src = fb + (size_t)spidx[g] * D_FEAT;
        for (int k = tid; k < 768; k += 256) feat[g][k] = src[k];
    }
    if (tid < 8){
        int p = spidx[tid];
        scc[0][tid] = cbp[p*3+0];
        scc[1][tid] = cbp[p*3+1];
        scc[2][tid] = cbp[p*3+2];
    }
    __syncthreads();

    // hidden = relu(cfeat @ W1^T + b1), 8 centers per W1 pass
    if (tid < C){
        float acc[8];
        const float bb = B1[tid];
        #pragma unroll
        for (int g = 0; g < 8; g++) acc[g] = bb;
        const float4* w4 = reinterpret_cast<const float4*>(W1 + (size_t)tid * 768);
        for (int k4 = 0; k4 < 192; k4++){
            float4 w = __ldg(&w4[k4]);
            #pragma unroll
            for (int g = 0; g < 8; g++){
                float4 f = *reinterpret_cast<const float4*>(&feat[g][k4*4]);
                acc[g] += f.x*w.x + f.y*w.y + f.z*w.z + f.w*w.w;
            }
        }
        #pragma unroll
        for (int g = 0; g < 8; g++) hid[g][tid] = fmaxf(acc[g], 0.f);
    }
    __syncthreads();

    // logits -> sigmoid (4 accumulator chains)
    if (tid < 8*S){
        int g = tid / S, s = tid - g*S;
        const float* w2 = W2 + (size_t)s * C;
        float a0 = B2[s], a1 = 0.f, a2 = 0.f, a3 = 0.f;
        for (int j = 0; j < C; j += 4){
            a0 += hid[g][j]   * w2[j];
            a1 += hid[g][j+1] * w2[j+1];
            a2 += hid[g][j+2] * w2[j+2];
            a3 += hid[g][j+3] * w2[j+3];
        }
        float a = (a0 + a1) + (a2 + a3);
        sprob[g][s] = 1.f / (1.f + expf(-a));
    }

    // safety
    if (scale == 0){
        if (tid < 8){
            float t = (scc[2][tid] - g_zstat[b][0]) / 5.0f;
            ssaf[tid] = 1.f + (1.f / (1.f + expf(-t))) * 0.95f;
        }
    } else if (scale == 1){
        if (tid < 8) ssaf[tid] = 1.f + expf(-(g_zstat[b][1] / 0.1f)) * 0.9f;
    } else {
        int cnt[8];
        float cx[8], cy[8], cz[8], aa[8];
        #pragma unroll
        for (int g = 0; g < 8; g++){
            cnt[g] = 0;
            cx[g] = scc[0][g]; cy[g] = scc[1][g]; cz[g] = scc[2][g];
            aa[g] = faddr(faddr(fmulr(cx[g],cx[g]), fmulr(cy[g],cy[g])), fmulr(cz[g],cz[g]));
        }
        for (int j = tid; j < N_PTS; j += 256){
            float bx = cbp[j*3+0], by = cbp[j*3+1], bz = cbp[j*3+2];
            float bb = faddr(faddr(fmulr(bx,bx), fmulr(by,by)), fmulr(bz,bz));
            #pragma unroll
            for (int g = 0; g < 8; g++){
                float dt = faddr(faddr(fmulr(cx[g],bx), fmulr(cy[g],by)), fmulr(cz[g],bz));
                float d2 = faddr(faddr(aa[g], bb), -fmulr(2.0f, dt));
                if (fmaxf(d2, 0.f) < 0.25f) cnt[g]++;
            }
        }
        #pragma unroll
        for (int g = 0; g < 8; g++) atomicAdd(&scnt[g], cnt[g]);
    }
    __syncthreads();
    if (scale == 2 && tid < 8)
        ssaf[tid] = 1.f + ((float)scnt[tid] / (float)N_PTS) * 0.95f;
    __syncthreads();

    if (tid < 8){
        float m = 0.f;
        for (int s = 0; s < S; s++) m += sprob[tid][s];
        m /= (float)S;
        g_final[b][scale][c0 + tid] = m * ssaf[tid];
    }
}

// ---------------- stable top-k ----------------
__global__ __launch_bounds__(32) void topk_kernel(){
    const int blk = blockIdx.x;
    const int b = blk / 3, sc = blk % 3;
    const int C   = (sc == 0) ? 256 : (sc == 1 ? 128 : 64);
    const int S   = (sc == 2) ? 8 : 16;
    const int off = (sc == 0) ? 0 : (sc == 1 ? 16 : 32);
    const int lane = threadIdx.x;

    __shared__ float fv[256];
    __shared__ int   taken[256];
    for (int j = lane; j < C; j += 32){ fv[j] = g_final[b][sc][j]; taken[j] = 0; }
    __syncwarp();

    for (int t = 0; t < S; t++){
        float bv = -1e30f; int bi = C;
        for (int j = lane; j < C; j += 32){
            if (!taken[j]){
                float v = fv[j];
                if (v > bv || (v == bv && j < bi)){ bv = v; bi = j; }
            }
        }
        for (int o = 16; o; o >>= 1){
            float ov = __shfl_down_sync(0xffffffffu, bv, o);
            int   oi = __shfl_down_sync(0xffffffffu, bi, o);
            if (ov > bv || (ov == bv && oi < bi)){ bv = ov; bi = oi; }
        }
        bi = __shfl_sync(0xffffffffu, bi, 0);
        if (lane == 0){ taken[bi] = 1; g_tok[b][off + t] = g_fps[b][bi]; }
        __syncwarp();
    }
}

// ---------------- token MLP + LayerNorm (one block per token) ----------------
__global__ __launch_bounds__(384) void mlp_kernel(const float* __restrict__ feats,
    const float* __restrict__ pW1, const float* __restrict__ pb1,
    const float* __restrict__ pW2, const float* __restrict__ pb2,
    const float* __restrict__ lng, const float* __restrict__ lnb,
    float* __restrict__ out){

    __shared__ float feat[768];
    __shared__ float hid[384];
    __shared__ float ov[768];
    __shared__ float red[32];

    const int blk = blockIdx.x;
    const int b = blk / 40, t = blk % 40;
    const int tid = threadIdx.x, lane = tid & 31, wid = tid >> 5;

    const int src = g_tok[b][t];
    const float* fs = feats + ((size_t)b * N_PTS + src) * D_FEAT;
    {
        const float4* f4 = reinterpret_cast<const float4*>(fs);
        float4* s4 = reinterpret_cast<float4*>(feat);
        if (tid < 192) s4[tid] = f4[tid];
    }
    __syncthreads();

    {   // hid = relu(tok @ pW1^T + pb1) — 4 independent accumulator chains
        const float4* w4 = reinterpret_cast<const float4*>(pW1 + (size_t)tid * 768);
        const float4* f4 = reinterpret_cast<const float4*>(feat);
        float a0 = 0.f, a1 = 0.f, a2 = 0.f, a3 = 0.f;
        #pragma unroll 4
        for (int k = 0; k < 192; k += 4){
            float4 w0 = __ldg(&w4[k]);
            float4 w1 = __ldg(&w4[k+1]);
            float4 w2 = __ldg(&w4[k+2]);
            float4 w3 = __ldg(&w4[k+3]);
            float4 f0 = f4[k],   f1 = f4[k+1];
            float4 f2 = f4[k+2], f3 = f4[k+3];
            a0 += f0.x*w0.x + f0.y*w0.y + f0.z*w0.z + f0.w*w0.w;
            a1 += f1.x*w1.x + f1.y*w1.y + f1.z*w1.z + f1.w*w1.w;
            a2 += f2.x*w2.x + f2.y*w2.y + f2.z*w2.z + f2.w*w2.w;
            a3 += f3.x*w3.x + f3.y*w3.y + f3.z*w3.z + f3.w*w3.w;
        }
        hid[tid] = fmaxf(pb1[tid] + ((a0 + a1) + (a2 + a3)), 0.f);
    }
    __syncthreads();

    #pragma unroll
    for (int h = 0; h < 2; h++){
        int o = tid + h * 384;
        const float4* w4 = reinterpret_cast<const float4*>(pW2 + (size_t)o * 384);
        const float4* f4 = reinterpret_cast<const float4*>(hid);
        float a0 = 0.f, a1 = 0.f, a2 = 0.f, a3 = 0.f;
        #pragma unroll 4
        for (int k = 0; k < 96; k += 4){
            float4 w0 = __ldg(&w4[k]);
            float4 w1 = __ldg(&w4[k+1]);
            float4 w2 = __ldg(&w4[k+2]);
            float4 w3 = __ldg(&w4[k+3]);
            float4 f0 = f4[k],   f1 = f4[k+1];
            float4 f2 = f4[k+2], f3 = f4[k+3];
            a0 += f0.x*w0.x + f0.y*w0.y + f0.z*w0.z + f0.w*w0.w;
            a1 += f1.x*w1.x + f1.y*w1.y + f1.z*w1.z + f1.w*w1.w;
            a2 += f2.x*w2.x + f2.y*w2.y + f2.z*w2.z + f2.w*w2.w;
            a3 += f3.x*w3.x + f3.y*w3.y + f3.z*w3.z + f3.w*w3.w;
        }
        ov[o] = pb2[o] + ((a0 + a1) + (a2 + a3));
    }
    __syncthreads();

    // LayerNorm over 768
    float s = ov[tid] + ov[tid + 384];
    for (int o = 16; o; o >>= 1) s += __shfl_down_sync(0xffffffffu, s, o);
    if (lane == 0) red[wid] = s;
    __syncthreads();
    if (tid < 32){
        float v = (tid < 12) ? red[tid] : 0.f;
        for (int o = 16; o; o >>= 1) v += __shfl_down_sync(0xffffffffu, v, o);
        if (tid == 0) red[0] = v;
    }
    __syncthreads();
    const float mu = red[0] * (1.f / 768.f);
    __syncthreads();

    const float d0 = ov[tid] - mu, d1 = ov[tid + 384] - mu;
    float s2 = d0*d0 + d1*d1;
    for (int o = 16; o; o >>= 1) s2 += __shfl_down_sync(0xffffffffu, s2, o);
    if (lane == 0) red[wid] = s2;
    __syncthreads();
    if (tid < 32){
        float v = (tid < 12) ? red[tid] : 0.f;
        for (int o = 16; o; o >>= 1) v += __shfl_down_sync(0xffffffffu, v, o);
        if (tid == 0) red[0] = v;
    }
    __syncthreads();
    const float var = red[0] * (1.f / 768.f);
    const float rs  = rsqrtf(var + 1e-5f);

    float* op = out + ((size_t)(b * 40 + t)) * 768;
    op[tid]       = d0 * rs * lng[tid]       + lnb[tid];
    op[tid + 384] = d1 * rs * lng[tid + 384] + lnb[tid + 384];
}

// ---------------- launch ----------------
extern "C" void kernel_launch(void* const* d_in, const int* in_sizes, int n_in,
                              void* d_out, int out_size){
    const float* feats  = (const float*)d_in[0];
    const float* coords = (const float*)d_in[1];
    const float* gW1 = (const float*)d_in[2];
    const float* gB1 = (const float*)d_in[3];
    const float* gW2 = (const float*)d_in[4];
    const float* gB2 = (const float*)d_in[5];
    const float* cW1 = (const float*)d_in[6];
    const float* cB1 = (const float*)d_in[7];
    const float* cW2 = (const float*)d_in[8];
    const float* cB2 = (const float*)d_in[9];
    const float* dW1 = (const float*)d_in[10];
    const float* dB1 = (const float*)d_in[11];
    const float* dW2 = (const float*)d_in[12];
    const float* dB2 = (const float*)d_in[13];
    const float* pW1 = (const float*)d_in[14];
    const float* pb1 = (const float*)d_in[15];
    const float* pW2 = (const float*)d_in[16];
    const float* pb2 = (const float*)d_in[17];
    const float* lng = (const float*)d_in[18];
    const float* lnb = (const float*)d_in[19];
    float* out = (float*)d_out;

    fps_kernel<<<2, 1024>>>(coords);
    score_kernel<<<112, 256>>>(feats, coords,
                               gW1, gB1, gW2, gB2,
                               cW1, cB1, cW2, cB2,
                               dW1, dB1, dW2, dB2);
    topk_kernel<<<6, 32>>>();
    mlp_kernel<<<80, 384>>>(feats, pW1, pb1, pW2, pb2, lng, lnb, out);
}

// round 3
// speedup vs baseline: 1.5684x; 1.5349x over previous
#include <cuda_runtime.h>
#include <math.h>
#include <stdint.h>

#define N_PTS 8192
#define D_FEAT 768

// ---------------- scratch (device globals; no allocs allowed) ----------------
__device__ int   g_fps[2][256];
__device__ float g_zstat[2][2];        // [b][0]=z mean, [b][1]=z var (ddof=1)
__device__ float g_final[2][3][256];   // per-scale scores
__device__ int   g_tok[2][40];         // selected point indices

__device__ __forceinline__ float fmulr(float a, float b){ return __fmul_rn(a,b); }
__device__ __forceinline__ float faddr(float a, float b){ return __fadd_rn(a,b); }

// ---- packed f32x2 helpers — per-lane IEEE RN, bit-identical to scalar RN ops
__device__ __forceinline__ unsigned long long pk2(float lo, float hi){
    unsigned long long r;
    asm("mov.b64 %0, {%1, %2};" : "=l"(r) : "f"(lo), "f"(hi));
    return r;
}
__device__ __forceinline__ void upk2(unsigned long long v, float& lo, float& hi){
    asm("mov.b64 {%0, %1}, %2;" : "=f"(lo), "=f"(hi) : "l"(v));
}
__device__ __forceinline__ unsigned long long add2(unsigned long long a, unsigned long long b){
    unsigned long long r;
    asm("add.rn.f32x2 %0, %1, %2;" : "=l"(r) : "l"(a), "l"(b));
    return r;
}
__device__ __forceinline__ unsigned long long mul2(unsigned long long a, unsigned long long b){
    unsigned long long r;
    asm("mul.rn.f32x2 %0, %1, %2;" : "=l"(r) : "l"(a), "l"(b));
    return r;
}

// ---------------- FPS (one block per batch, fully register-resident) ----------
// Value-only block argmax (atomicMax on nonneg float bits) + exact index
// selection via the sqrt-tie pass (min index with __fsqrt_rn(d2)==sref),
// which reproduces JAX argmax-over-sqrt semantics exactly.
// NO dynamic indexing of the per-thread arrays anywhere -> stays in registers.
__global__ __launch_bounds__(512) void fps_kernel(const float* __restrict__ coords){
    __shared__ float redf[16];
    __shared__ float s_tmp;
    __shared__ int   s_valbits[2];
    __shared__ int   s_win[2];

    const int b    = blockIdx.x;
    const int tid  = threadIdx.x;
    const int lane = tid & 31;
    const int wid  = tid >> 5;
    const float* cb = coords + (size_t)b * N_PTS * 3;

    // Each thread owns 16 points: j = tid + k*512.
    float d2[16];
    unsigned long long px2[8], py2[8], pz2[8];
    float zs = 0.f;
    {
        float tx[16], ty[16], tz[16];
        #pragma unroll
        for (int k = 0; k < 16; k++){
            const int j = tid + (k << 9);
            tx[k] = cb[j*3+0];
            ty[k] = cb[j*3+1];
            tz[k] = cb[j*3+2];
            zs += tz[k];
            d2[k] = __int_as_float(0x7f800000);
        }
        #pragma unroll
        for (int k = 0; k < 8; k++){
            px2[k] = pk2(tx[2*k], tx[2*k+1]);
            py2[k] = pk2(ty[2*k], ty[2*k+1]);
            pz2[k] = pk2(tz[2*k], tz[2*k+1]);
        }
    }

    // ---- z mean ----
    for (int o = 16; o; o >>= 1) zs += __shfl_down_sync(0xffffffffu, zs, o);
    if (lane == 0) redf[wid] = zs;
    __syncthreads();
    if (tid < 16){
        float v = redf[tid];
        for (int o = 8; o; o >>= 1) v += __shfl_down_sync(0x0000ffffu, v, o);
        if (tid == 0) s_tmp = v;
    }
    __syncthreads();
    const float zmean = s_tmp / (float)N_PTS;
    // ---- z var (ddof=1) ----
    float zd = 0.f;
    #pragma unroll
    for (int k = 0; k < 8; k++){
        float z0, z1; upk2(pz2[k], z0, z1);
        float a = z0 - zmean, c = z1 - zmean;
        zd += a*a + c*c;
    }
    for (int o = 16; o; o >>= 1) zd += __shfl_down_sync(0xffffffffu, zd, o);
    if (lane == 0) redf[wid] = zd;
    __syncthreads();
    if (tid < 16){
        float v = redf[tid];
        for (int o = 8; o; o >>= 1) v += __shfl_down_sync(0x0000ffffu, v, o);
        if (tid == 0){
            g_zstat[b][0] = zmean;
            g_zstat[b][1] = v / (float)(N_PTS - 1);
            g_fps[b][0]   = 0;
        }
    }
    if (tid < 2){ s_valbits[tid] = INT32_MIN; s_win[tid] = N_PTS; }
    __syncthreads();

    int w = 0;
    for (int s = 1; s < 256; s++){
        const int p = s & 1;
        // all threads read the last-selected coords (L1 broadcast)
        const float lx = __ldg(cb + w*3 + 0);
        const float ly = __ldg(cb + w*3 + 1);
        const float lz = __ldg(cb + w*3 + 2);
        const unsigned long long nlx2 = pk2(-lx, -lx);
        const unsigned long long nly2 = pk2(-ly, -ly);
        const unsigned long long nlz2 = pk2(-lz, -lz);

        float tmax = -1.f;
        #pragma unroll
        for (int k = 0; k < 8; k++){
            // (p - L) via p + (-L): exact; square-then-sum (x2+y2)+z2, RN
            unsigned long long dx = add2(px2[k], nlx2);
            unsigned long long dy = add2(py2[k], nly2);
            unsigned long long dz = add2(pz2[k], nlz2);
            unsigned long long sm = add2(add2(mul2(dx,dx), mul2(dy,dy)), mul2(dz,dz));
            float lo, hi; upk2(sm, lo, hi);
            float a = fminf(d2[2*k],   lo);
            float c = fminf(d2[2*k+1], hi);
            d2[2*k]   = a;
            d2[2*k+1] = c;
            tmax = fmaxf(tmax, fmaxf(a, c));
        }
        float wmax = tmax;
        for (int o = 16; o; o >>= 1) wmax = fmaxf(wmax, __shfl_down_sync(0xffffffffu, wmax, o));
        if (lane == 0) atomicMax(&s_valbits[p], __float_as_int(wmax));
        __syncthreads();                                    // bar 1

        const float m2 = __int_as_float(s_valbits[p]);
        if (tid == 0){ s_valbits[1-p] = INT32_MIN; s_win[1-p] = N_PTS; }
        const float thr = m2 - m2 * 1e-6f;
        if (tmax >= thr){
            const float sref = __fsqrt_rn(m2);
            #pragma unroll
            for (int k = 0; k < 16; k++){
                if (d2[k] >= thr){
                    if (__fsqrt_rn(d2[k]) == sref) atomicMin(&s_win[p], tid + (k << 9));
                }
            }
        }
        __syncthreads();                                    // bar 2

        w = s_win[p];
        if ((w & 511) == tid){
            const int kk = w >> 9;
            #pragma unroll
            for (int k = 0; k < 16; k++) if (k == kk) d2[k] = 0.f;
            g_fps[b][s] = w;
        }
    }
}

// ---------------- scoring (8 centers per block, coalesced W1) ----------------
__global__ __launch_bounds__(256) void score_kernel(
    const float* __restrict__ feats, const float* __restrict__ coords,
    const float* __restrict__ gW1, const float* __restrict__ gB1,
    const float* __restrict__ gW2, const float* __restrict__ gB2,
    const float* __restrict__ cW1, const float* __restrict__ cB1,
    const float* __restrict__ cW2, const float* __restrict__ cB2,
    const float* __restrict__ dW1, const float* __restrict__ dB1,
    const float* __restrict__ dW2, const float* __restrict__ dB2){

    __shared__ __align__(16) float feat[8][768];
    __shared__ float hid [8][260];
    __shared__ float sprob[8][16];
    __shared__ float ssaf[8];
    __shared__ int   spidx[8];
    __shared__ int   scnt[8];
    __shared__ float scc[3][8];

    const int blk = blockIdx.x;
    const int b   = blk / 56;
    const int r   = blk % 56;
    int scale, C, S, c0;
    const float *W1, *B1, *W2, *B2;
    if (r < 32){ scale=0; C=256; S=16; c0=r*8;       W1=gW1; B1=gB1; W2=gW2; B2=gB2; }
    else if (r < 48){ scale=1; C=128; S=16; c0=(r-32)*8; W1=cW1; B1=cB1; W2=cW2; B2=cB2; }
    else { scale=2; C=64; S=8; c0=(r-48)*8;          W1=dW1; B1=dB1; W2=dW2; B2=dB2; }

    const int tid  = threadIdx.x;
    const int lane = tid & 31;
    const int wid  = tid >> 5;              // 0..7
    if (tid < 8){ spidx[tid] = g_fps[b][c0 + tid]; scnt[tid] = 0; }
    __syncthreads();

    const float* fb  = feats  + (size_t)b * N_PTS * D_FEAT;
    const float* cbp = coords + (size_t)b * N_PTS * 3;
    #pragma unroll
    for (int g = 0; g < 8; g++){
        const float* src = fb + (size_t)spidx[g] * D_FEAT;
        for (int k = tid; k < 768; k += 256) feat[g][k] = src[k];
    }
    if (tid < 8){
        int p = spidx[tid];
        scc[0][tid] = cbp[p*3+0];
        scc[1][tid] = cbp[p*3+1];
        scc[2][tid] = cbp[p*3+2];
    }
    __syncthreads();

    // hidden = relu(cfeat @ W1^T + b1) — warp-per-row, coalesced weight reads
    {
        const int nrows = C >> 3;           // rows per warp
        for (int i = 0; i < nrows; i++){
            const int j = wid + (i << 3);
            const float4* w4 = reinterpret_cast<const float4*>(W1 + (size_t)j * 768);
            float4 wv[6];
            #pragma unroll
            for (int c = 0; c < 6; c++) wv[c] = __ldg(&w4[lane + (c << 5)]);
            float acc[8];
            #pragma unroll
            for (int g = 0; g < 8; g++){
                const float4* f4 = reinterpret_cast<const float4*>(&feat[g][0]);
                float a = 0.f;
                #pragma unroll
                for (int c = 0; c < 6; c++){
                    float4 f = f4[lane + (c << 5)];
                    a += f.x*wv[c].x + f.y*wv[c].y + f.z*wv[c].z + f.w*wv[c].w;
                }
                acc[g] = a;
            }
            #pragma unroll
            for (int g = 0; g < 8; g++)
                for (int o = 16; o; o >>= 1)
                    acc[g] += __shfl_down_sync(0xffffffffu, acc[g], o);
            if (lane == 0){
                const float bb = B1[j];
                #pragma unroll
                for (int g = 0; g < 8; g++) hid[g][j] = fmaxf(acc[g] + bb, 0.f);
            }
        }
    }
    __syncthreads();

    // logits -> sigmoid
    if (tid < 8*S){
        int g = tid / S, s = tid - g*S;
        const float* w2 = W2 + (size_t)s * C;
        float a0 = B2[s], a1 = 0.f, a2 = 0.f, a3 = 0.f;
        for (int j = 0; j < C; j += 4){
            a0 += hid[g][j]   * w2[j];
            a1 += hid[g][j+1] * w2[j+1];
            a2 += hid[g][j+2] * w2[j+2];
            a3 += hid[g][j+3] * w2[j+3];
        }
        float a = (a0 + a1) + (a2 + a3);
        sprob[g][s] = 1.f / (1.f + expf(-a));
    }

    // safety
    if (scale == 0){
        if (tid < 8){
            float t = (scc[2][tid] - g_zstat[b][0]) / 5.0f;
            ssaf[tid] = 1.f + (1.f / (1.f + expf(-t))) * 0.95f;
        }
    } else if (scale == 1){
        if (tid < 8) ssaf[tid] = 1.f + expf(-(g_zstat[b][1] / 0.1f)) * 0.9f;
    } else {
        int cnt[8];
        float cx[8], cy[8], cz[8], aa[8];
        #pragma unroll
        for (int g = 0; g < 8; g++){
            cnt[g] = 0;
            cx[g] = scc[0][g]; cy[g] = scc[1][g]; cz[g] = scc[2][g];
            aa[g] = faddr(faddr(fmulr(cx[g],cx[g]), fmulr(cy[g],cy[g])), fmulr(cz[g],cz[g]));
        }
        for (int j = tid; j < N_PTS; j += 256){
            float bx = cbp[j*3+0], by = cbp[j*3+1], bz = cbp[j*3+2];
            float bb = faddr(faddr(fmulr(bx,bx), fmulr(by,by)), fmulr(bz,bz));
            #pragma unroll
            for (int g = 0; g < 8; g++){
                float dt = faddr(faddr(fmulr(cx[g],bx), fmulr(cy[g],by)), fmulr(cz[g],bz));
                float dd = faddr(faddr(aa[g], bb), -fmulr(2.0f, dt));
                if (fmaxf(dd, 0.f) < 0.25f) cnt[g]++;
            }
        }
        #pragma unroll
        for (int g = 0; g < 8; g++) atomicAdd(&scnt[g], cnt[g]);
    }
    __syncthreads();
    if (scale == 2 && tid < 8)
        ssaf[tid] = 1.f + ((float)scnt[tid] / (float)N_PTS) * 0.95f;
    __syncthreads();

    if (tid < 8){
        float m = 0.f;
        for (int s = 0; s < S; s++) m += sprob[tid][s];
        m /= (float)S;
        g_final[b][scale][c0 + tid] = m * ssaf[tid];
    }
}

// ---------------- stable top-k ----------------
__global__ __launch_bounds__(32) void topk_kernel(){
    const int blk = blockIdx.x;
    const int b = blk / 3, sc = blk % 3;
    const int C   = (sc == 0) ? 256 : (sc == 1 ? 128 : 64);
    const int S   = (sc == 2) ? 8 : 16;
    const int off = (sc == 0) ? 0 : (sc == 1 ? 16 : 32);
    const int lane = threadIdx.x;

    __shared__ float fv[256];
    __shared__ int   taken[256];
    for (int j = lane; j < C; j += 32){ fv[j] = g_final[b][sc][j]; taken[j] = 0; }
    __syncwarp();

    for (int t = 0; t < S; t++){
        float bv = -1e30f; int bi = C;
        for (int j = lane; j < C; j += 32){
            if (!taken[j]){
                float v = fv[j];
                if (v > bv || (v == bv && j < bi)){ bv = v; bi = j; }
            }
        }
        for (int o = 16; o; o >>= 1){
            float ov = __shfl_down_sync(0xffffffffu, bv, o);
            int   oi = __shfl_down_sync(0xffffffffu, bi, o);
            if (ov > bv || (ov == bv && oi < bi)){ bv = ov; bi = oi; }
        }
        bi = __shfl_sync(0xffffffffu, bi, 0);
        if (lane == 0){ taken[bi] = 1; g_tok[b][off + t] = g_fps[b][bi]; }
        __syncwarp();
    }
}

// ---------------- token MLP + LayerNorm (warp-per-output, coalesced) --------
__global__ __launch_bounds__(384) void mlp_kernel(const float* __restrict__ feats,
    const float* __restrict__ pW1, const float* __restrict__ pb1,
    const float* __restrict__ pW2, const float* __restrict__ pb2,
    const float* __restrict__ lng, const float* __restrict__ lnb,
    float* __restrict__ out){

    __shared__ __align__(16) float feat[768];
    __shared__ __align__(16) float hid[384];
    __shared__ float ov[768];
    __shared__ float red[32];

    const int blk = blockIdx.x;
    const int b = blk / 40, t = blk % 40;
    const int tid = threadIdx.x, lane = tid & 31, wid = tid >> 5;   // wid 0..11

    const int src = g_tok[b][t];
    const float* fs = feats + ((size_t)b * N_PTS + src) * D_FEAT;
    if (tid < 192)
        reinterpret_cast<float4*>(feat)[tid] = reinterpret_cast<const float4*>(fs)[tid];
    __syncthreads();

    // layer 1: 384 outputs, warp computes 32 (2 in flight), coalesced rows
    {
        const float4* f4 = reinterpret_cast<const float4*>(feat);
        for (int i = 0; i < 32; i += 2){
            const int o0 = (wid << 5) + i, o1 = o0 + 1;
            const float4* wa4 = reinterpret_cast<const float4*>(pW1 + (size_t)o0 * 768);
            const float4* wb4 = reinterpret_cast<const float4*>(pW1 + (size_t)o1 * 768);
            float a0 = 0.f, a1 = 0.f;
            #pragma unroll
            for (int c = 0; c < 6; c++){
                float4 f  = f4[lane + (c << 5)];
                float4 wa = __ldg(&wa4[lane + (c << 5)]);
                float4 wb = __ldg(&wb4[lane + (c << 5)]);
                a0 += f.x*wa.x + f.y*wa.y + f.z*wa.z + f.w*wa.w;
                a1 += f.x*wb.x + f.y*wb.y + f.z*wb.z + f.w*wb.w;
            }
            for (int o = 16; o; o >>= 1){
                a0 += __shfl_down_sync(0xffffffffu, a0, o);
                a1 += __shfl_down_sync(0xffffffffu, a1, o);
            }
            if (lane == 0){
                hid[o0] = fmaxf(a0 + pb1[o0], 0.f);
                hid[o1] = fmaxf(a1 + pb1[o1], 0.f);
            }
        }
    }
    __syncthreads();

    // layer 2: 768 outputs, warp computes 64 (2 in flight)
    {
        const float4* h4 = reinterpret_cast<const float4*>(hid);
        for (int i = 0; i < 64; i += 2){
            const int o0 = (wid << 6) + i, o1 = o0 + 1;
            const float4* wa4 = reinterpret_cast<const float4*>(pW2 + (size_t)o0 * 384);
            const float4* wb4 = reinterpret_cast<const float4*>(pW2 + (size_t)o1 * 384);
            float a0 = 0.f, a1 = 0.f;
            #pragma unroll
            for (int c = 0; c < 3; c++){
                float4 h  = h4[lane + (c << 5)];
                float4 wa = __ldg(&wa4[lane + (c << 5)]);
                float4 wb = __ldg(&wb4[lane + (c << 5)]);
                a0 += h.x*wa.x + h.y*wa.y + h.z*wa.z + h.w*wa.w;
                a1 += h.x*wb.x + h.y*wb.y + h.z*wb.z + h.w*wb.w;
            }
            for (int o = 16; o; o >>= 1){
                a0 += __shfl_down_sync(0xffffffffu, a0, o);
                a1 += __shfl_down_sync(0xffffffffu, a1, o);
            }
            if (lane == 0){
                ov[o0] = a0 + pb2[o0];
                ov[o1] = a1 + pb2[o1];
            }
        }
    }
    __syncthreads();

    // LayerNorm over 768
    float s = ov[tid] + ov[tid + 384];
    for (int o = 16; o; o >>= 1) s += __shfl_down_sync(0xffffffffu, s, o);
    if (lane == 0) red[wid] = s;
    __syncthreads();
    if (tid < 32){
        float v = (tid < 12) ? red[tid] : 0.f;
        for (int o = 16; o; o >>= 1) v += __shfl_down_sync(0xffffffffu, v, o);
        if (tid == 0) red[0] = v;
    }
    __syncthreads();
    const float mu = red[0] * (1.f / 768.f);
    __syncthreads();

    const float d0 = ov[tid] - mu, d1 = ov[tid + 384] - mu;
    float s2 = d0*d0 + d1*d1;
    for (int o = 16; o; o >>= 1) s2 += __shfl_down_sync(0xffffffffu, s2, o);
    if (lane == 0) red[wid] = s2;
    __syncthreads();
    if (tid < 32){
        float v = (tid < 12) ? red[tid] : 0.f;
        for (int o = 16; o; o >>= 1) v += __shfl_down_sync(0xffffffffu, v, o);
        if (tid == 0) red[0] = v;
    }
    __syncthreads();
    const float var = red[0] * (1.f / 768.f);
    const float rs  = rsqrtf(var + 1e-5f);

    float* op = out + ((size_t)(b * 40 + t)) * 768;
    op[tid]       = d0 * rs * lng[tid]       + lnb[tid];
    op[tid + 384] = d1 * rs * lng[tid + 384] + lnb[tid + 384];
}

// ---------------- launch ----------------
extern "C" void kernel_launch(void* const* d_in, const int* in_sizes, int n_in,
                              void* d_out, int out_size){
    const float* feats  = (const float*)d_in[0];
    const float* coords = (const float*)d_in[1];
    const float* gW1 = (const float*)d_in[2];
    const float* gB1 = (const float*)d_in[3];
    const float* gW2 = (const float*)d_in[4];
    const float* gB2 = (const float*)d_in[5];
    const float* cW1 = (const float*)d_in[6];
    const float* cB1 = (const float*)d_in[7];
    const float* cW2 = (const float*)d_in[8];
    const float* cB2 = (const float*)d_in[9];
    const float* dW1 = (const float*)d_in[10];
    const float* dB1 = (const float*)d_in[11];
    const float* dW2 = (const float*)d_in[12];
    const float* dB2 = (const float*)d_in[13];
    const float* pW1 = (const float*)d_in[14];
    const float* pb1 = (const float*)d_in[15];
    const float* pW2 = (const float*)d_in[16];
    const float* pb2 = (const float*)d_in[17];
    const float* lng = (const float*)d_in[18];
    const float* lnb = (const float*)d_in[19];
    float* out = (float*)d_out;

    fps_kernel<<<2, 512>>>(coords);
    score_kernel<<<112, 256>>>(feats, coords,
                               gW1, gB1, gW2, gB2,
                               cW1, cB1, cW2, cB2,
                               dW1, dB1, dW2, dB2);
    topk_kernel<<<6, 32>>>();
    mlp_kernel<<<80, 384>>>(feats, pW1, pb1, pW2, pb2, lng, lnb, out);
}

// round 4
// speedup vs baseline: 2.0531x; 1.3090x over previous
#include <cuda_runtime.h>
#include <math.h>
#include <stdint.h>

#define N_PTS 8192
#define D_FEAT 768

// ---------------- scratch (device globals; no allocs allowed) ----------------
__device__ int   g_fps[2][256];
__device__ float g_zstat[2][2];        // [b][0]=z mean, [b][1]=z var (ddof=1)
__device__ float g_final[2][3][256];   // per-scale scores
__device__ int   g_tok[2][40];         // selected point indices
__device__ float g_hid[80][384];       // mlp layer-1 activations
__device__ float g_ov [80][768];       // mlp layer-2 pre-LN outputs

__device__ __forceinline__ float fmulr(float a, float b){ return __fmul_rn(a,b); }
__device__ __forceinline__ float faddr(float a, float b){ return __fadd_rn(a,b); }

// ---- packed f32x2 helpers — per-lane IEEE RN, bit-identical to scalar RN ops
__device__ __forceinline__ unsigned long long pk2(float lo, float hi){
    unsigned long long r;
    asm("mov.b64 %0, {%1, %2};" : "=l"(r) : "f"(lo), "f"(hi));
    return r;
}
__device__ __forceinline__ void upk2(unsigned long long v, float& lo, float& hi){
    asm("mov.b64 {%0, %1}, %2;" : "=f"(lo), "=f"(hi) : "l"(v));
}
__device__ __forceinline__ unsigned long long add2(unsigned long long a, unsigned long long b){
    unsigned long long r;
    asm("add.rn.f32x2 %0, %1, %2;" : "=l"(r) : "l"(a), "l"(b));
    return r;
}
__device__ __forceinline__ unsigned long long mul2(unsigned long long a, unsigned long long b){
    unsigned long long r;
    asm("mul.rn.f32x2 %0, %1, %2;" : "=l"(r) : "l"(a), "l"(b));
    return r;
}
__device__ __forceinline__ unsigned redux_max_u32(unsigned v){
    unsigned r;
    asm("redux.sync.max.u32 %0, %1, 0xffffffff;" : "=r"(r) : "r"(v));
    return r;
}

// ---------------- FPS (one block per batch, register-resident, redux) --------
// Exact JAX argmax-over-sqrt semantics: block max of d2 (monotone under sqrt),
// then min index among points whose __fsqrt_rn(d2) equals __fsqrt_rn(max d2).
__global__ __launch_bounds__(1024) void fps_kernel(const float* __restrict__ coords){
    __shared__ unsigned redw[32];
    __shared__ float redf[32];
    __shared__ float s_tmp;
    __shared__ int   s_win[2];

    const int b    = blockIdx.x;
    const int tid  = threadIdx.x;
    const int lane = tid & 31;
    const int wid  = tid >> 5;
    const float* cb = coords + (size_t)b * N_PTS * 3;

    // Each thread owns 8 points: j = tid + k*1024.
    float d2[8];
    unsigned long long px2[4], py2[4], pz2[4];
    float zs = 0.f;
    {
        float tx[8], ty[8], tz[8];
        #pragma unroll
        for (int k = 0; k < 8; k++){
            const int j = tid + (k << 10);
            tx[k] = cb[j*3+0];
            ty[k] = cb[j*3+1];
            tz[k] = cb[j*3+2];
            zs += tz[k];
            d2[k] = __int_as_float(0x7f800000);
        }
        #pragma unroll
        for (int k = 0; k < 4; k++){
            px2[k] = pk2(tx[2*k], tx[2*k+1]);
            py2[k] = pk2(ty[2*k], ty[2*k+1]);
            pz2[k] = pk2(tz[2*k], tz[2*k+1]);
        }
    }

    // ---- z mean ----
    for (int o = 16; o; o >>= 1) zs += __shfl_down_sync(0xffffffffu, zs, o);
    if (lane == 0) redf[wid] = zs;
    __syncthreads();
    if (wid == 0){
        float v = redf[lane];
        for (int o = 16; o; o >>= 1) v += __shfl_down_sync(0xffffffffu, v, o);
        if (lane == 0) s_tmp = v;
    }
    __syncthreads();
    const float zmean = s_tmp / (float)N_PTS;
    // ---- z var (ddof=1) ----
    float zd = 0.f;
    #pragma unroll
    for (int k = 0; k < 4; k++){
        float z0, z1; upk2(pz2[k], z0, z1);
        float a = z0 - zmean, c = z1 - zmean;
        zd += a*a + c*c;
    }
    for (int o = 16; o; o >>= 1) zd += __shfl_down_sync(0xffffffffu, zd, o);
    if (lane == 0) redf[wid] = zd;
    __syncthreads();
    if (wid == 0){
        float v = redf[lane];
        for (int o = 16; o; o >>= 1) v += __shfl_down_sync(0xffffffffu, v, o);
        if (lane == 0){
            g_zstat[b][0] = zmean;
            g_zstat[b][1] = v / (float)(N_PTS - 1);
            g_fps[b][0]   = 0;
        }
    }
    if (tid < 2) s_win[tid] = N_PTS;
    __syncthreads();

    int w = 0;
    for (int s = 1; s < 256; s++){
        const int p = s & 1;
        // last-selected coords: L1-resident after the initial full sweep
        const float lx = __ldg(cb + w*3 + 0);
        const float ly = __ldg(cb + w*3 + 1);
        const float lz = __ldg(cb + w*3 + 2);
        const unsigned long long nlx2 = pk2(-lx, -lx);
        const unsigned long long nly2 = pk2(-ly, -ly);
        const unsigned long long nlz2 = pk2(-lz, -lz);

        float tmax = -1.f;
        #pragma unroll
        for (int k = 0; k < 4; k++){
            unsigned long long dx = add2(px2[k], nlx2);
            unsigned long long dy = add2(py2[k], nly2);
            unsigned long long dz = add2(pz2[k], nlz2);
            unsigned long long sm = add2(add2(mul2(dx,dx), mul2(dy,dy)), mul2(dz,dz));
            float lo, hi; upk2(sm, lo, hi);
            float a = fminf(d2[2*k],   lo);
            float c = fminf(d2[2*k+1], hi);
            d2[2*k]   = a;
            d2[2*k+1] = c;
            tmax = fmaxf(tmax, fmaxf(a, c));
        }
        // block max: warp redux -> smem -> warp redux (single barrier)
        unsigned wm = redux_max_u32(__float_as_uint(tmax));
        if (lane == 0) redw[wid] = wm;
        __syncthreads();                                    // bar 1
        const float m2 = __uint_as_float(redux_max_u32(redw[lane]));
        if (tid == 0) s_win[1-p] = N_PTS;                   // reset next slot
        const float thr = m2 - m2 * 1e-6f;
        if (tmax >= thr){
            const float sref = __fsqrt_rn(m2);
            #pragma unroll
            for (int k = 0; k < 8; k++){
                if (d2[k] >= thr){
                    if (__fsqrt_rn(d2[k]) == sref) atomicMin(&s_win[p], tid + (k << 10));
                }
            }
        }
        __syncthreads();                                    // bar 2
        w = s_win[p];
        if (tid == 0) g_fps[b][s] = w;
        // no d2 zeroing needed: next iteration dist(w,w)=0 -> fmin absorbs it
    }
}

// ---------------- scoring (8 centers per block, coalesced W1) ----------------
__global__ __launch_bounds__(256) void score_kernel(
    const float* __restrict__ feats, const float* __restrict__ coords,
    const float* __restrict__ gW1, const float* __restrict__ gB1,
    const float* __restrict__ gW2, const float* __restrict__ gB2,
    const float* __restrict__ cW1, const float* __restrict__ cB1,
    const float* __restrict__ cW2, const float* __restrict__ cB2,
    const float* __restrict__ dW1, const float* __restrict__ dB1,
    const float* __restrict__ dW2, const float* __restrict__ dB2){

    __shared__ __align__(16) float feat[8][768];
    __shared__ float hid [8][260];
    __shared__ float sprob[8][16];
    __shared__ float ssaf[8];
    __shared__ int   spidx[8];
    __shared__ int   scnt[8];
    __shared__ float scc[3][8];

    const int blk = blockIdx.x;
    const int b   = blk / 56;
    const int r   = blk % 56;
    int scale, C, S, c0;
    const float *W1, *B1, *W2, *B2;
    if (r < 32){ scale=0; C=256; S=16; c0=r*8;       W1=gW1; B1=gB1; W2=gW2; B2=gB2; }
    else if (r < 48){ scale=1; C=128; S=16; c0=(r-32)*8; W1=cW1; B1=cB1; W2=cW2; B2=cB2; }
    else { scale=2; C=64; S=8; c0=(r-48)*8;          W1=dW1; B1=dB1; W2=dW2; B2=dB2; }

    const int tid  = threadIdx.x;
    const int lane = tid & 31;
    const int wid  = tid >> 5;              // 0..7
    if (tid < 8){ spidx[tid] = g_fps[b][c0 + tid]; scnt[tid] = 0; }
    __syncthreads();

    const float* fb  = feats  + (size_t)b * N_PTS * D_FEAT;
    const float* cbp = coords + (size_t)b * N_PTS * 3;
    #pragma unroll
    for (int g = 0; g < 8; g++){
        const float* src = fb + (size_t)spidx[g] * D_FEAT;
        for (int k = tid; k < 768; k += 256) feat[g][k] = src[k];
    }
    if (tid < 8){
        int p = spidx[tid];
        scc[0][tid] = cbp[p*3+0];
        scc[1][tid] = cbp[p*3+1];
        scc[2][tid] = cbp[p*3+2];
    }
    __syncthreads();

    // hidden = relu(cfeat @ W1^T + b1) — warp-per-row, coalesced weight reads
    {
        const int nrows = C >> 3;
        for (int i = 0; i < nrows; i++){
            const int j = wid + (i << 3);
            const float4* w4 = reinterpret_cast<const float4*>(W1 + (size_t)j * 768);
            float4 wv[6];
            #pragma unroll
            for (int c = 0; c < 6; c++) wv[c] = __ldg(&w4[lane + (c << 5)]);
            float acc[8];
            #pragma unroll
            for (int g = 0; g < 8; g++){
                const float4* f4 = reinterpret_cast<const float4*>(&feat[g][0]);
                float a = 0.f;
                #pragma unroll
                for (int c = 0; c < 6; c++){
                    float4 f = f4[lane + (c << 5)];
                    a += f.x*wv[c].x + f.y*wv[c].y + f.z*wv[c].z + f.w*wv[c].w;
                }
                acc[g] = a;
            }
            #pragma unroll
            for (int g = 0; g < 8; g++)
                for (int o = 16; o; o >>= 1)
                    acc[g] += __shfl_down_sync(0xffffffffu, acc[g], o);
            if (lane == 0){
                const float bb = B1[j];
                #pragma unroll
                for (int g = 0; g < 8; g++) hid[g][j] = fmaxf(acc[g] + bb, 0.f);
            }
        }
    }
    __syncthreads();

    // logits -> sigmoid
    if (tid < 8*S){
        int g = tid / S, s = tid - g*S;
        const float* w2 = W2 + (size_t)s * C;
        float a0 = B2[s], a1 = 0.f, a2 = 0.f, a3 = 0.f;
        for (int j = 0; j < C; j += 4){
            a0 += hid[g][j]   * w2[j];
            a1 += hid[g][j+1] * w2[j+1];
            a2 += hid[g][j+2] * w2[j+2];
            a3 += hid[g][j+3] * w2[j+3];
        }
        float a = (a0 + a1) + (a2 + a3);
        sprob[g][s] = 1.f / (1.f + expf(-a));
    }

    // safety
    if (scale == 0){
        if (tid < 8){
            float t = (scc[2][tid] - g_zstat[b][0]) / 5.0f;
            ssaf[tid] = 1.f + (1.f / (1.f + expf(-t))) * 0.95f;
        }
    } else if (scale == 1){
        if (tid < 8) ssaf[tid] = 1.f + expf(-(g_zstat[b][1] / 0.1f)) * 0.9f;
    } else {
        int cnt[8];
        float cx[8], cy[8], cz[8], aa[8];
        #pragma unroll
        for (int g = 0; g < 8; g++){
            cnt[g] = 0;
            cx[g] = scc[0][g]; cy[g] = scc[1][g]; cz[g] = scc[2][g];
            aa[g] = faddr(faddr(fmulr(cx[g],cx[g]), fmulr(cy[g],cy[g])), fmulr(cz[g],cz[g]));
        }
        for (int j = tid; j < N_PTS; j += 256){
            float bx = cbp[j*3+0], by = cbp[j*3+1], bz = cbp[j*3+2];
            float bb = faddr(faddr(fmulr(bx,bx), fmulr(by,by)), fmulr(bz,bz));
            #pragma unroll
            for (int g = 0; g < 8; g++){
                float dt = faddr(faddr(fmulr(cx[g],bx), fmulr(cy[g],by)), fmulr(cz[g],bz));
                float dd = faddr(faddr(aa[g], bb), -fmulr(2.0f, dt));
                if (fmaxf(dd, 0.f) < 0.25f) cnt[g]++;
            }
        }
        #pragma unroll
        for (int g = 0; g < 8; g++) atomicAdd(&scnt[g], cnt[g]);
    }
    __syncthreads();
    if (scale == 2 && tid < 8)
        ssaf[tid] = 1.f + ((float)scnt[tid] / (float)N_PTS) * 0.95f;
    __syncthreads();

    if (tid < 8){
        float m = 0.f;
        for (int s = 0; s < S; s++) m += sprob[tid][s];
        m /= (float)S;
        g_final[b][scale][c0 + tid] = m * ssaf[tid];
    }
}

// ---------------- stable top-k ----------------
__global__ __launch_bounds__(32) void topk_kernel(){
    const int blk = blockIdx.x;
    const int b = blk / 3, sc = blk % 3;
    const int C   = (sc == 0) ? 256 : (sc == 1 ? 128 : 64);
    const int S   = (sc == 2) ? 8 : 16;
    const int off = (sc == 0) ? 0 : (sc == 1 ? 16 : 32);
    const int lane = threadIdx.x;

    __shared__ float fv[256];
    __shared__ int   taken[256];
    for (int j = lane; j < C; j += 32){ fv[j] = g_final[b][sc][j]; taken[j] = 0; }
    __syncwarp();

    for (int t = 0; t < S; t++){
        float bv = -1e30f; int bi = C;
        for (int j = lane; j < C; j += 32){
            if (!taken[j]){
                float v = fv[j];
                if (v > bv || (v == bv && j < bi)){ bv = v; bi = j; }
            }
        }
        for (int o = 16; o; o >>= 1){
            float ov = __shfl_down_sync(0xffffffffu, bv, o);
            int   oi = __shfl_down_sync(0xffffffffu, bi, o);
            if (ov > bv || (ov == bv && oi < bi)){ bv = ov; bi = oi; }
        }
        bi = __shfl_sync(0xffffffffu, bi, 0);
        if (lane == 0){ taken[bi] = 1; g_tok[b][off + t] = g_fps[b][bi]; }
        __syncwarp();
    }
}

// ---------------- mlp layer 1: hid = relu(tok @ W1^T + b1) -------------------
// grid (20 token-groups, 3 output-tiles of 128), block 128.
// 4 tokens per block: weights staged coalesced -> smem (pad 65, conflict-free),
// features transposed in smem so one LDS.128 broadcast feeds 4 FMAs.
__global__ __launch_bounds__(128) void mlp1_kernel(const float* __restrict__ feats,
    const float* __restrict__ pW1, const float* __restrict__ pb1){

    __shared__ __align__(16) float featT[768][4];
    __shared__ float wS[128*65];
    __shared__ int stok[4];

    const int tg = blockIdx.x, ot = blockIdx.y;
    const int tid = threadIdx.x;

    if (tid < 4){
        int tt = tg*4 + tid;
        int b = tt / 40;
        stok[tid] = b * N_PTS + g_tok[b][tt - b*40];
    }
    __syncthreads();
    #pragma unroll
    for (int t = 0; t < 4; t++){
        const float4* src = reinterpret_cast<const float4*>(feats + (size_t)stok[t] * D_FEAT);
        for (int i = tid; i < 192; i += 128){
            float4 v = __ldg(&src[i]);
            featT[i*4+0][t] = v.x; featT[i*4+1][t] = v.y;
            featT[i*4+2][t] = v.z; featT[i*4+3][t] = v.w;
        }
    }

    float a0 = 0.f, a1 = 0.f, a2 = 0.f, a3 = 0.f;
    const int o = ot*128 + tid;
    for (int k0 = 0; k0 < 768; k0 += 64){
        __syncthreads();
        const float* wbase = pW1 + (size_t)(ot*128) * 768 + k0;
        #pragma unroll
        for (int j = 0; j < 16; j++){
            int idx = tid + j*128;
            int row = idx >> 4, c4 = idx & 15;
            float4 v = __ldg(reinterpret_cast<const float4*>(wbase + (size_t)row*768) + c4);
            float* d = &wS[row*65 + c4*4];
            d[0] = v.x; d[1] = v.y; d[2] = v.z; d[3] = v.w;
        }
        __syncthreads();
        const float* wr = &wS[tid*65];
        #pragma unroll
        for (int kk = 0; kk < 64; kk++){
            float4 f = *reinterpret_cast<const float4*>(&featT[k0+kk][0]);
            float w = wr[kk];
            a0 += f.x*w; a1 += f.y*w; a2 += f.z*w; a3 += f.w*w;
        }
    }
    const float bb = pb1[o];
    g_hid[tg*4+0][o] = fmaxf(a0 + bb, 0.f);
    g_hid[tg*4+1][o] = fmaxf(a1 + bb, 0.f);
    g_hid[tg*4+2][o] = fmaxf(a2 + bb, 0.f);
    g_hid[tg*4+3][o] = fmaxf(a3 + bb, 0.f);
}

// ---------------- mlp layer 2: ov = hid @ W2^T + b2 --------------------------
// grid (20 token-groups, 6 output-tiles of 128), block 128.
__global__ __launch_bounds__(128) void mlp2_kernel(
    const float* __restrict__ pW2, const float* __restrict__ pb2){

    __shared__ __align__(16) float featT[384][4];
    __shared__ float wS[128*65];

    const int tg = blockIdx.x, ot = blockIdx.y;
    const int tid = threadIdx.x;

    #pragma unroll
    for (int t = 0; t < 4; t++){
        const float4* src = reinterpret_cast<const float4*>(&g_hid[tg*4+t][0]);
        for (int i = tid; i < 96; i += 128){
            float4 v = src[i];
            featT[i*4+0][t] = v.x; featT[i*4+1][t] = v.y;
            featT[i*4+2][t] = v.z; featT[i*4+3][t] = v.w;
        }
    }

    float a0 = 0.f, a1 = 0.f, a2 = 0.f, a3 = 0.f;
    const int o = ot*128 + tid;
    for (int k0 = 0; k0 < 384; k0 += 64){
        __syncthreads();
        const float* wbase = pW2 + (size_t)(ot*128) * 384 + k0;
        #pragma unroll
        for (int j = 0; j < 16; j++){
            int idx = tid + j*128;
            int row = idx >> 4, c4 = idx & 15;
            float4 v = __ldg(reinterpret_cast<const float4*>(wbase + (size_t)row*384) + c4);
            float* d = &wS[row*65 + c4*4];
            d[0] = v.x; d[1] = v.y; d[2] = v.z; d[3] = v.w;
        }
        __syncthreads();
        const float* wr = &wS[tid*65];
        #pragma unroll
        for (int kk = 0; kk < 64; kk++){
            float4 f = *reinterpret_cast<const float4*>(&featT[k0+kk][0]);
            float w = wr[kk];
            a0 += f.x*w; a1 += f.y*w; a2 += f.z*w; a3 += f.w*w;
        }
    }
    const float bb = pb2[o];
    g_ov[tg*4+0][o] = a0 + bb;
    g_ov[tg*4+1][o] = a1 + bb;
    g_ov[tg*4+2][o] = a2 + bb;
    g_ov[tg*4+3][o] = a3 + bb;
}

// ---------------- LayerNorm (one block per token) ----------------------------
__global__ __launch_bounds__(384) void ln_kernel(
    const float* __restrict__ lng, const float* __restrict__ lnb,
    float* __restrict__ out){

    __shared__ float red[32];
    const int t = blockIdx.x;           // 0..79
    const int tid = threadIdx.x, lane = tid & 31, wid = tid >> 5;

    const float v0 = g_ov[t][tid];
    const float v1 = g_ov[t][tid + 384];

    float s = v0 + v1;
    for (int o = 16; o; o >>= 1) s += __shfl_down_sync(0xffffffffu, s, o);
    if (lane == 0) red[wid] = s;
    __syncthreads();
    if (tid < 32){
        float v = (tid < 12) ? red[tid] : 0.f;
        for (int o = 16; o; o >>= 1) v += __shfl_down_sync(0xffffffffu, v, o);
        if (tid == 0) red[0] = v;
    }
    __syncthreads();
    const float mu = red[0] * (1.f / 768.f);
    __syncthreads();

    const float d0 = v0 - mu, d1 = v1 - mu;
    float s2 = d0*d0 + d1*d1;
    for (int o = 16; o; o >>= 1) s2 += __shfl_down_sync(0xffffffffu, s2, o);
    if (lane == 0) red[wid] = s2;
    __syncthreads();
    if (tid < 32){
        float v = (tid < 12) ? red[tid] : 0.f;
        for (int o = 16; o; o >>= 1) v += __shfl_down_sync(0xffffffffu, v, o);
        if (tid == 0) red[0] = v;
    }
    __syncthreads();
    const float var = red[0] * (1.f / 768.f);
    const float rs  = rsqrtf(var + 1e-5f);

    float* op = out + (size_t)t * 768;
    op[tid]       = d0 * rs * lng[tid]       + lnb[tid];
    op[tid + 384] = d1 * rs * lng[tid + 384] + lnb[tid + 384];
}

// ---------------- launch ----------------
extern "C" void kernel_launch(void* const* d_in, const int* in_sizes, int n_in,
                              void* d_out, int out_size){
    const float* feats  = (const float*)d_in[0];
    const float* coords = (const float*)d_in[1];
    const float* gW1 = (const float*)d_in[2];
    const float* gB1 = (const float*)d_in[3];
    const float* gW2 = (const float*)d_in[4];
    const float* gB2 = (const float*)d_in[5];
    const float* cW1 = (const float*)d_in[6];
    const float* cB1 = (const float*)d_in[7];
    const float* cW2 = (const float*)d_in[8];
    const float* cB2 = (const float*)d_in[9];
    const float* dW1 = (const float*)d_in[10];
    const float* dB1 = (const float*)d_in[11];
    const float* dW2 = (const float*)d_in[12];
    const float* dB2 = (const float*)d_in[13];
    const float* pW1 = (const float*)d_in[14];
    const float* pb1 = (const float*)d_in[15];
    const float* pW2 = (const float*)d_in[16];
    const float* pb2 = (const float*)d_in[17];
    const float* lng = (const float*)d_in[18];
    const float* lnb = (const float*)d_in[19];
    float* out = (float*)d_out;

    fps_kernel<<<2, 1024>>>(coords);
    score_kernel<<<112, 256>>>(feats, coords,
                               gW1, gB1, gW2, gB2,
                               cW1, cB1, cW2, cB2,
                               dW1, dB1, dW2, dB2);
    topk_kernel<<<6, 32>>>();
    mlp1_kernel<<<dim3(20,3), 128>>>(feats, pW1, pb1);
    mlp2_kernel<<<dim3(20,6), 128>>>(pW2, pb2);
    ln_kernel<<<80, 384>>>(lng, lnb, out);
}